// round 8
// baseline (speedup 1.0000x reference)
#include <cuda_runtime.h>
#include <math.h>

#define C_DIM 1280
#define HW    9216
#define WIMG  96
#define N_ID  16
#define D_IN  512
#define B_SZ  8
#define M_ROWS 128
#define KCHUNK 8

#define PX_CTA 64
#define CHUNKS (HW / PX_CTA)     // 144
#define HALF_C (C_DIM / 2)       // 640
#define UNR 8

// ---------------- scratch ----------------
__device__ float g_h[M_ROWS * C_DIM];
__device__ float g_part[KCHUNK * M_ROWS * C_DIM];
__device__ float g_pt[B_SZ * C_DIM * N_ID];    // projected [b][c][n]

// ---------------- f32x2 helpers ----------------
__device__ __forceinline__ unsigned long long fma2(unsigned long long a,
                                                   unsigned long long b,
                                                   unsigned long long c) {
    unsigned long long d;
    asm("fma.rn.f32x2 %0, %1, %2, %3;" : "=l"(d) : "l"(a), "l"(b), "l"(c));
    return d;
}
__device__ __forceinline__ unsigned long long packf2(float lo, float hi) {
    unsigned long long r;
    asm("mov.b64 %0, {%1, %2};" : "=l"(r) : "f"(lo), "f"(hi));
    return r;
}
__device__ __forceinline__ float2 unpackf2(unsigned long long v) {
    float2 r;
    asm("mov.b64 {%0, %1}, %2;" : "=f"(r.x), "=f"(r.y) : "l"(v));
    return r;
}

// ---------------- f32x2 GEMM tile 32x32, 256 thr ----------------
__device__ __forceinline__ void gemm_f2(const float* __restrict__ A,
                                        const float* __restrict__ Wm,
                                        float* __restrict__ Out,
                                        int ldA, int kt0, int ktEnd, int Nc,
                                        const float* __restrict__ bias, bool gelu) {
    __shared__ float sAt[32][34];
    __shared__ float sB[32][33];
    int t = threadIdx.x, tj = t & 31, tr = t >> 5;
    int rowBase = blockIdx.y * 32, colBase = blockIdx.x * 32;
    unsigned long long acc2[2] = {0ull, 0ull};

    for (int kt = kt0; kt < ktEnd; kt += 32) {
#pragma unroll
        for (int s = 0; s < 4; s++) {
            int idx = t + s * 256;
            int r = idx >> 5, kk = idx & 31;
            sAt[kk][r] = A[(size_t)(rowBase + r) * ldA + kt + kk];
            sB[r][kk]  = Wm[(size_t)(kt + r) * Nc + colBase + kk];
        }
        __syncthreads();
#pragma unroll
        for (int k = 0; k < 32; k++) {
            float bv = sB[k][tj];
            unsigned long long bp = packf2(bv, bv);
            const unsigned long long* ap = (const unsigned long long*)&sAt[k][tr * 4];
            acc2[0] = fma2(ap[0], bp, acc2[0]);
            acc2[1] = fma2(ap[1], bp, acc2[1]);
        }
        __syncthreads();
    }
    float2 a0 = unpackf2(acc2[0]), a1 = unpackf2(acc2[1]);
    float vals[4] = {a0.x, a0.y, a1.x, a1.y};
#pragma unroll
    for (int i = 0; i < 4; i++) {
        float v = vals[i] + (bias ? bias[colBase + tj] : 0.f);
        if (gelu) v = 0.5f * v * (1.f + erff(v * 0.70710678f));
        Out[(size_t)(rowBase + tr * 4 + i) * Nc + colBase + tj] = v;
    }
}

__global__ __launch_bounds__(256) void mlp1_kernel(const float* __restrict__ E,
                                                   const float* __restrict__ W1,
                                                   const float* __restrict__ b1) {
    gemm_f2(E, W1, g_h, D_IN, 0, D_IN, C_DIM, b1, true);
}
__global__ __launch_bounds__(256) void mlp2_kernel(const float* __restrict__ W2) {
    int z = blockIdx.z;
    int kspan = C_DIM / KCHUNK;      // 160
    gemm_f2(g_h, W2, g_part + (size_t)z * M_ROWS * C_DIM,
            C_DIM, z * kspan, (z + 1) * kspan, C_DIM, nullptr, false);
}

// ---------------- reduce split-K + bias + normalize -> g_pt[b][c][16] ----
__global__ __launch_bounds__(128) void norm_kernel(const float* __restrict__ b2v) {
    int r = blockIdx.x, t = threadIdx.x;
    int b = r >> 4, n = r & 15;
    float v[10];
    float ss = 0.f;
#pragma unroll
    for (int i = 0; i < 10; i++) {
        int c = t + i * 128;
        size_t o = (size_t)r * C_DIM + c;
        float x = b2v[c];
#pragma unroll
        for (int z = 0; z < KCHUNK; z++)
            x += g_part[o + (size_t)z * M_ROWS * C_DIM];
        v[i] = x;
        ss = fmaf(x, x, ss);
    }
#pragma unroll
    for (int o = 16; o > 0; o >>= 1) ss += __shfl_xor_sync(0xffffffffu, ss, o);
    __shared__ float sw[4];
    if ((t & 31) == 0) sw[t >> 5] = ss;
    __syncthreads();
    float tot = sw[0] + sw[1] + sw[2] + sw[3];
    float scale = 35.7770876f / (sqrtf(tot) + 1e-6f);
#pragma unroll
    for (int i = 0; i < 10; i++) {
        int c = t + i * 128;
        g_pt[((size_t)b * C_DIM + c) * N_ID + n] = v[i] * scale;
    }
}

// ---------------- fused main kernel (L2-tiled, 2 threads/pixel) ----------------
// 128 thr, 64 px/CTA, grid 1152 (144 blk/batch), 80KB dyn smem, 2 CTAs/SM
__global__ __launch_bounds__(128, 2) void fused_kernel(const float* __restrict__ hidden,
                                                       const float* __restrict__ bboxes,
                                                       float* __restrict__ out) {
    extern __shared__ float sp[];                       // [1280][16]
    __shared__ float sred[PX_CTA][18];                  // half-1 partials: 16 dots + ss
    __shared__ unsigned long long swp[PX_CTA][8];       // final packed weights
    __shared__ int sx1[N_ID], sy1[N_ID], sx2[N_ID], sy2[N_ID], semp[N_ID];

    int t = threadIdx.x;
    int blk = blockIdx.x;
    int b = blk / CHUNKS;
    int pbase = (blk % CHUNKS) * PX_CTA;
    int pix = t & 63;
    int half = t >> 6;
    int px = pbase + pix;

    const float4* src = (const float4*)(g_pt + (size_t)b * C_DIM * N_ID);
    float4* dst = (float4*)sp;
#pragma unroll
    for (int i = 0; i < 40; i++) dst[t + i * 128] = src[t + i * 128];

    if (t < N_ID) {
        float bx1 = bboxes[t * 4 + 0] * 96.f;
        float by1 = bboxes[t * 4 + 1] * 96.f;
        float bx2 = bboxes[t * 4 + 2] * 96.f;
        float by2 = bboxes[t * 4 + 3] * 96.f;
        int X1 = (int)floorf(fminf(fmaxf(bx1, 0.f), 96.f));
        int Y1 = (int)floorf(fminf(fmaxf(by1, 0.f), 96.f));
        int X2 = (int)floorf(fminf(fmaxf(bx2, 0.f), 96.f));
        int Y2 = (int)floorf(fminf(fmaxf(by2, 0.f), 96.f));
        sx1[t] = X1; sy1[t] = Y1; sx2[t] = X2; sy2[t] = Y2;
        semp[t] = (X1 >= X2) || (Y1 >= Y2);
    }
    __syncthreads();

    int allempty = 1;
#pragma unroll
    for (int n = 0; n < N_ID; n++) allempty &= semp[n];

    int y = px / WIMG;
    int x = px - y * WIMG;
    int c0 = half * HALF_C;
    const float* hp = hidden + (size_t)b * C_DIM * HW + (size_t)c0 * HW + px;

    // ---- pass 1: this thread's 640-channel partial sumsq + 16 dots ----
    unsigned long long acc[8];
#pragma unroll
    for (int k = 0; k < 8; k++) acc[k] = 0ull;
    float ss = 0.f;

    float hA[UNR], hB[UNR];
#pragma unroll
    for (int i = 0; i < UNR; i++) hA[i] = hp[(size_t)i * HW];

#define P1_COMPUTE(HBUF, CB)                                                     \
    {                                                                            \
        _Pragma("unroll")                                                        \
        for (int i = 0; i < UNR; i++) {                                          \
            ss = fmaf(HBUF[i], HBUF[i], ss);                                     \
            unsigned long long hx = packf2(HBUF[i], HBUF[i]);                    \
            const ulonglong2* p2 =                                               \
                (const ulonglong2*)(sp + ((c0 + (CB) + i) << 4));                \
            ulonglong2 q0 = p2[0], q1 = p2[1], q2 = p2[2], q3 = p2[3];           \
            acc[0] = fma2(hx, q0.x, acc[0]);                                     \
            acc[1] = fma2(hx, q0.y, acc[1]);                                     \
            acc[2] = fma2(hx, q1.x, acc[2]);                                     \
            acc[3] = fma2(hx, q1.y, acc[3]);                                     \
            acc[4] = fma2(hx, q2.x, acc[4]);                                     \
            acc[5] = fma2(hx, q2.y, acc[5]);                                     \
            acc[6] = fma2(hx, q3.x, acc[6]);                                     \
            acc[7] = fma2(hx, q3.y, acc[7]);                                     \
        }                                                                        \
    }

    for (int cb = 0; cb < HALF_C; cb += 2 * UNR) {
#pragma unroll
        for (int i = 0; i < UNR; i++)
            hB[i] = hp[(size_t)(cb + UNR + i) * HW];
        P1_COMPUTE(hA, cb);
        if (cb + 2 * UNR < HALF_C) {
#pragma unroll
            for (int i = 0; i < UNR; i++)
                hA[i] = hp[(size_t)(cb + 2 * UNR + i) * HW];
        }
        P1_COMPUTE(hB, cb + UNR);
    }

    // ---- cross-half reduction via smem ----
    if (half == 1) {
#pragma unroll
        for (int k = 0; k < 8; k++) {
            float2 a = unpackf2(acc[k]);
            sred[pix][2 * k]     = a.x;
            sred[pix][2 * k + 1] = a.y;
        }
        sred[pix][16] = ss;
    }
    __syncthreads();

    if (half == 0) {
        float d[N_ID];
#pragma unroll
        for (int k = 0; k < 8; k++) {
            float2 a = unpackf2(acc[k]);
            d[2 * k]     = a.x + sred[pix][2 * k];
            d[2 * k + 1] = a.y + sred[pix][2 * k + 1];
        }
        float sstot = ss + sred[pix][16];

        const float invT = 1.999996f;           // 1/(0.5+1e-6)
        float inv = invT / (sqrtf(sstot) + 1e-6f);
        float w[N_ID];
        float sum = 0.f;
#pragma unroll
        for (int n = 0; n < N_ID; n++) {
            int m = allempty | ((y >= sy1[n]) & (y < sy2[n]) &
                                (x >= sx1[n]) & (x < sx2[n]));
            float s = 1.f / (1.f + __expf(-d[n] * inv));
            float wv = m ? s : 0.f;
            w[n] = wv;
            sum += wv;
        }
        float is = 1.f / (sum + 1e-6f);
#pragma unroll
        for (int k = 0; k < 8; k++)
            swp[pix][k] = packf2(__powf(w[2 * k] * is, 1.2f),
                                 __powf(w[2 * k + 1] * is, 1.2f));
    }
    __syncthreads();

    unsigned long long wp[8];
#pragma unroll
    for (int k = 0; k < 8; k++) wp[k] = swp[pix][k];

    // ---- pass 2: out = hidden + 1.5*sum_n w[n]*p[n,c] (re-read hits L2) ----
    float* op = out + (size_t)b * C_DIM * HW + (size_t)c0 * HW + px;

#define P2_COMPUTE(HBUF, CB)                                                     \
    {                                                                            \
        _Pragma("unroll")                                                        \
        for (int i = 0; i < UNR; i++) {                                          \
            const ulonglong2* pq =                                               \
                (const ulonglong2*)(sp + ((c0 + (CB) + i) << 4));                \
            ulonglong2 q0 = pq[0], q1 = pq[1], q2 = pq[2], q3 = pq[3];           \
            unsigned long long s0 = 0ull;                                        \
            s0 = fma2(wp[0], q0.x, s0);                                          \
            s0 = fma2(wp[1], q0.y, s0);                                          \
            s0 = fma2(wp[2], q1.x, s0);                                          \
            s0 = fma2(wp[3], q1.y, s0);                                          \
            s0 = fma2(wp[4], q2.x, s0);                                          \
            s0 = fma2(wp[5], q2.y, s0);                                          \
            s0 = fma2(wp[6], q3.x, s0);                                          \
            s0 = fma2(wp[7], q3.y, s0);                                          \
            float2 a = unpackf2(s0);                                             \
            float o = fmaf(1.5f, a.x + a.y, HBUF[i]);                            \
            __stcs(op + (size_t)((CB) + i) * HW, o);                             \
        }                                                                        \
    }

#pragma unroll
    for (int i = 0; i < UNR; i++) hA[i] = hp[(size_t)i * HW];
    for (int cb = 0; cb < HALF_C; cb += 2 * UNR) {
#pragma unroll
        for (int i = 0; i < UNR; i++)
            hB[i] = hp[(size_t)(cb + UNR + i) * HW];
        P2_COMPUTE(hA, cb);
        if (cb + 2 * UNR < HALF_C) {
#pragma unroll
            for (int i = 0; i < UNR; i++)
                hA[i] = hp[(size_t)(cb + 2 * UNR + i) * HW];
        }
        P2_COMPUTE(hB, cb + UNR);
    }
}

// ---------------- launch ----------------
extern "C" void kernel_launch(void* const* d_in, const int* in_sizes, int n_in,
                              void* d_out, int out_size) {
    const float* hidden = (const float*)d_in[0];
    const float* emb    = (const float*)d_in[1];
    const float* bbox   = (const float*)d_in[2];
    const float* W1     = (const float*)d_in[3];
    const float* b1v    = (const float*)d_in[4];
    const float* W2     = (const float*)d_in[5];
    const float* b2v    = (const float*)d_in[6];
    float* outp = (float*)d_out;

    mlp1_kernel<<<dim3(C_DIM / 32, M_ROWS / 32), 256>>>(emb, W1, b1v);
    mlp2_kernel<<<dim3(C_DIM / 32, M_ROWS / 32, KCHUNK), 256>>>(W2);
    norm_kernel<<<M_ROWS, 128>>>(b2v);

    cudaFuncSetAttribute(fused_kernel, cudaFuncAttributeMaxDynamicSharedMemorySize,
                         C_DIM * N_ID * (int)sizeof(float));
    fused_kernel<<<B_SZ * CHUNKS, 128, C_DIM * N_ID * sizeof(float)>>>(hidden, bbox, outp);
}

// round 9
// speedup vs baseline: 1.5309x; 1.5309x over previous
#include <cuda_runtime.h>
#include <math.h>

#define C_DIM 1280
#define HW    9216
#define WIMG  96
#define N_ID  16
#define D_IN  512
#define B_SZ  8
#define M_ROWS 128
#define KCHUNK 8

// ---------------- scratch ----------------
__device__ float g_h[M_ROWS * C_DIM];
__device__ float g_part[KCHUNK * M_ROWS * C_DIM];
__device__ float g_pt[B_SZ * C_DIM * N_ID];    // projected [b][c][n]

// ---------------- f32x2 helpers ----------------
__device__ __forceinline__ unsigned long long fma2(unsigned long long a,
                                                   unsigned long long b,
                                                   unsigned long long c) {
    unsigned long long d;
    asm("fma.rn.f32x2 %0, %1, %2, %3;" : "=l"(d) : "l"(a), "l"(b), "l"(c));
    return d;
}
__device__ __forceinline__ unsigned long long packf2(float lo, float hi) {
    unsigned long long r;
    asm("mov.b64 %0, {%1, %2};" : "=l"(r) : "f"(lo), "f"(hi));
    return r;
}
__device__ __forceinline__ float2 unpackf2(unsigned long long v) {
    float2 r;
    asm("mov.b64 {%0, %1}, %2;" : "=f"(r.x), "=f"(r.y) : "l"(v));
    return r;
}

// ---------------- f32x2 GEMM tile 32x32, 256 thr ----------------
__device__ __forceinline__ void gemm_f2(const float* __restrict__ A,
                                        const float* __restrict__ Wm,
                                        float* __restrict__ Out,
                                        int ldA, int kt0, int ktEnd, int Nc,
                                        const float* __restrict__ bias, bool gelu) {
    __shared__ float sAt[32][34];
    __shared__ float sB[32][33];
    int t = threadIdx.x, tj = t & 31, tr = t >> 5;
    int rowBase = blockIdx.y * 32, colBase = blockIdx.x * 32;
    unsigned long long acc2[2] = {0ull, 0ull};

    for (int kt = kt0; kt < ktEnd; kt += 32) {
#pragma unroll
        for (int s = 0; s < 4; s++) {
            int idx = t + s * 256;
            int r = idx >> 5, kk = idx & 31;
            sAt[kk][r] = A[(size_t)(rowBase + r) * ldA + kt + kk];
            sB[r][kk]  = Wm[(size_t)(kt + r) * Nc + colBase + kk];
        }
        __syncthreads();
#pragma unroll
        for (int k = 0; k < 32; k++) {
            float bv = sB[k][tj];
            unsigned long long bp = packf2(bv, bv);
            const unsigned long long* ap = (const unsigned long long*)&sAt[k][tr * 4];
            acc2[0] = fma2(ap[0], bp, acc2[0]);
            acc2[1] = fma2(ap[1], bp, acc2[1]);
        }
        __syncthreads();
    }
    float2 a0 = unpackf2(acc2[0]), a1 = unpackf2(acc2[1]);
    float vals[4] = {a0.x, a0.y, a1.x, a1.y};
#pragma unroll
    for (int i = 0; i < 4; i++) {
        float v = vals[i] + (bias ? bias[colBase + tj] : 0.f);
        if (gelu) v = 0.5f * v * (1.f + erff(v * 0.70710678f));
        Out[(size_t)(rowBase + tr * 4 + i) * Nc + colBase + tj] = v;
    }
}

__global__ __launch_bounds__(256) void mlp1_kernel(const float* __restrict__ E,
                                                   const float* __restrict__ W1,
                                                   const float* __restrict__ b1) {
    gemm_f2(E, W1, g_h, D_IN, 0, D_IN, C_DIM, b1, true);
}
__global__ __launch_bounds__(256) void mlp2_kernel(const float* __restrict__ W2) {
    int z = blockIdx.z;
    int kspan = C_DIM / KCHUNK;      // 160
    gemm_f2(g_h, W2, g_part + (size_t)z * M_ROWS * C_DIM,
            C_DIM, z * kspan, (z + 1) * kspan, C_DIM, nullptr, false);
}

// ---------------- reduce split-K + bias + normalize -> g_pt[b][c][16] ----
__global__ __launch_bounds__(128) void norm_kernel(const float* __restrict__ b2v) {
    int r = blockIdx.x, t = threadIdx.x;
    int b = r >> 4, n = r & 15;
    float v[10];
    float ss = 0.f;
#pragma unroll
    for (int i = 0; i < 10; i++) {
        int c = t + i * 128;
        size_t o = (size_t)r * C_DIM + c;
        float x = b2v[c];
#pragma unroll
        for (int z = 0; z < KCHUNK; z++)
            x += g_part[o + (size_t)z * M_ROWS * C_DIM];
        v[i] = x;
        ss = fmaf(x, x, ss);
    }
#pragma unroll
    for (int o = 16; o > 0; o >>= 1) ss += __shfl_xor_sync(0xffffffffu, ss, o);
    __shared__ float sw[4];
    if ((t & 31) == 0) sw[t >> 5] = ss;
    __syncthreads();
    float tot = sw[0] + sw[1] + sw[2] + sw[3];
    float scale = 35.7770876f / (sqrtf(tot) + 1e-6f);
#pragma unroll
    for (int i = 0; i < 10; i++) {
        int c = t + i * 128;
        g_pt[((size_t)b * C_DIM + c) * N_ID + n] = v[i] * scale;
    }
}

// ---------------- fused main kernel (4-stage pipelined) ----------------
// 128 thr, 2 px/thread, 256 px/CTA, grid 288 (36 blk/batch), 80KB smem, 2 CTAs/SM
#define UNR 8          // channels per batch; 4 batches in flight, step 32
__global__ __launch_bounds__(128, 2) void fused_kernel(const float* __restrict__ hidden,
                                                       const float* __restrict__ bboxes,
                                                       float* __restrict__ out) {
    extern __shared__ float sp[];               // [1280][16]
    __shared__ int sx1[N_ID], sy1[N_ID], sx2[N_ID], sy2[N_ID], semp[N_ID];

    int t = threadIdx.x;
    int blk = blockIdx.x;
    int b = blk / 36;
    int px = (blk % 36) * 256 + 2 * t;          // even; pair never crosses a row

    const float4* src = (const float4*)(g_pt + (size_t)b * C_DIM * N_ID);
    float4* dst = (float4*)sp;
#pragma unroll
    for (int i = 0; i < 40; i++) dst[t + i * 128] = src[t + i * 128];

    if (t < N_ID) {
        float bx1 = bboxes[t * 4 + 0] * 96.f;
        float by1 = bboxes[t * 4 + 1] * 96.f;
        float bx2 = bboxes[t * 4 + 2] * 96.f;
        float by2 = bboxes[t * 4 + 3] * 96.f;
        int X1 = (int)floorf(fminf(fmaxf(bx1, 0.f), 96.f));
        int Y1 = (int)floorf(fminf(fmaxf(by1, 0.f), 96.f));
        int X2 = (int)floorf(fminf(fmaxf(bx2, 0.f), 96.f));
        int Y2 = (int)floorf(fminf(fmaxf(by2, 0.f), 96.f));
        sx1[t] = X1; sy1[t] = Y1; sx2[t] = X2; sy2[t] = Y2;
        semp[t] = (X1 >= X2) || (Y1 >= Y2);
    }
    __syncthreads();

    int allempty = 1;
#pragma unroll
    for (int n = 0; n < N_ID; n++) allempty &= semp[n];

    int y = px / WIMG;
    int x = px - y * WIMG;
    const float* hp = hidden + (size_t)b * C_DIM * HW + px;

    // ---- pass 1: sumsq + 16 dots for 2 px; 4-stage pipeline ----
    unsigned long long acc0[8], acc1[8];
#pragma unroll
    for (int k = 0; k < 8; k++) { acc0[k] = 0ull; acc1[k] = 0ull; }
    float ss0 = 0.f, ss1 = 0.f;

    float2 h0[UNR], h1[UNR], h2[UNR], h3[UNR];

#define LOADB(BUF, CB)                                                           \
    {                                                                            \
        _Pragma("unroll")                                                        \
        for (int i = 0; i < UNR; i++)                                            \
            BUF[i] = *(const float2*)(hp + (size_t)((CB) + i) * HW);             \
    }
#define LOADB_G(BUF, CB)                                                         \
    if ((CB) < C_DIM) LOADB(BUF, CB)

#define P1_COMPUTE(HBUF, CB)                                                     \
    {                                                                            \
        _Pragma("unroll")                                                        \
        for (int i = 0; i < UNR; i++) {                                          \
            ss0 = fmaf(HBUF[i].x, HBUF[i].x, ss0);                               \
            ss1 = fmaf(HBUF[i].y, HBUF[i].y, ss1);                               \
            unsigned long long hx = packf2(HBUF[i].x, HBUF[i].x);                \
            unsigned long long hy = packf2(HBUF[i].y, HBUF[i].y);                \
            const ulonglong2* p2 = (const ulonglong2*)(sp + (((CB) + i) << 4));  \
            ulonglong2 q0 = p2[0], q1 = p2[1], q2 = p2[2], q3 = p2[3];           \
            acc0[0] = fma2(hx, q0.x, acc0[0]);  acc1[0] = fma2(hy, q0.x, acc1[0]); \
            acc0[1] = fma2(hx, q0.y, acc0[1]);  acc1[1] = fma2(hy, q0.y, acc1[1]); \
            acc0[2] = fma2(hx, q1.x, acc0[2]);  acc1[2] = fma2(hy, q1.x, acc1[2]); \
            acc0[3] = fma2(hx, q1.y, acc0[3]);  acc1[3] = fma2(hy, q1.y, acc1[3]); \
            acc0[4] = fma2(hx, q2.x, acc0[4]);  acc1[4] = fma2(hy, q2.x, acc1[4]); \
            acc0[5] = fma2(hx, q2.y, acc0[5]);  acc1[5] = fma2(hy, q2.y, acc1[5]); \
            acc0[6] = fma2(hx, q3.x, acc0[6]);  acc1[6] = fma2(hy, q3.x, acc1[6]); \
            acc0[7] = fma2(hx, q3.y, acc0[7]);  acc1[7] = fma2(hy, q3.y, acc1[7]); \
        }                                                                        \
    }

    LOADB(h0, 0)
    LOADB(h1, UNR)
    LOADB(h2, 2 * UNR)
    for (int cb = 0; cb < C_DIM; cb += 4 * UNR) {
        LOADB(h3, cb + 3 * UNR)
        P1_COMPUTE(h0, cb)
        LOADB_G(h0, cb + 4 * UNR)
        P1_COMPUTE(h1, cb + UNR)
        LOADB_G(h1, cb + 5 * UNR)
        P1_COMPUTE(h2, cb + 2 * UNR)
        LOADB_G(h2, cb + 6 * UNR)
        P1_COMPUTE(h3, cb + 3 * UNR)
    }

    // ---- weights for both pixels ----
    const float invT = 1.999996f;               // 1/(0.5+1e-6)
    float inv0 = invT / (sqrtf(ss0) + 1e-6f);
    float inv1 = invT / (sqrtf(ss1) + 1e-6f);
    float w0[N_ID], w1[N_ID];
    float sum0 = 0.f, sum1 = 0.f;
#pragma unroll
    for (int k = 0; k < 8; k++) {
        float2 d0 = unpackf2(acc0[k]);
        float2 d1 = unpackf2(acc1[k]);
#pragma unroll
        for (int j = 0; j < 2; j++) {
            int n = 2 * k + j;
            float da = (j == 0) ? d0.x : d0.y;
            float db = (j == 0) ? d1.x : d1.y;
            int ybox = (y >= sy1[n]) & (y < sy2[n]);
            int m0 = allempty | (ybox & (x >= sx1[n]) & (x < sx2[n]));
            int m1 = allempty | (ybox & ((x + 1) >= sx1[n]) & ((x + 1) < sx2[n]));
            float s0 = 1.f / (1.f + __expf(-da * inv0));
            float s1 = 1.f / (1.f + __expf(-db * inv1));
            float wv0 = m0 ? s0 : 0.f;
            float wv1 = m1 ? s1 : 0.f;
            w0[n] = wv0; sum0 += wv0;
            w1[n] = wv1; sum1 += wv1;
        }
    }
    float is0 = 1.f / (sum0 + 1e-6f);
    float is1 = 1.f / (sum1 + 1e-6f);
    unsigned long long wp0[8], wp1[8];
#pragma unroll
    for (int k = 0; k < 8; k++) {
        wp0[k] = packf2(__powf(w0[2 * k] * is0, 1.2f), __powf(w0[2 * k + 1] * is0, 1.2f));
        wp1[k] = packf2(__powf(w1[2 * k] * is1, 1.2f), __powf(w1[2 * k + 1] * is1, 1.2f));
    }

    // ---- pass 2: out = hidden + 1.5*sum_n w[n]*p[n,c]; 4-stage pipeline ----
    float* op = out + (size_t)b * C_DIM * HW + px;

#define P2_COMPUTE(HBUF, CB)                                                     \
    {                                                                            \
        _Pragma("unroll")                                                        \
        for (int i = 0; i < UNR; i++) {                                          \
            const ulonglong2* pq = (const ulonglong2*)(sp + (((CB) + i) << 4));  \
            ulonglong2 q0 = pq[0], q1 = pq[1], q2 = pq[2], q3 = pq[3];           \
            unsigned long long s0 = 0ull, s1 = 0ull;                             \
            s0 = fma2(wp0[0], q0.x, s0);  s1 = fma2(wp1[0], q0.x, s1);           \
            s0 = fma2(wp0[1], q0.y, s0);  s1 = fma2(wp1[1], q0.y, s1);           \
            s0 = fma2(wp0[2], q1.x, s0);  s1 = fma2(wp1[2], q1.x, s1);           \
            s0 = fma2(wp0[3], q1.y, s0);  s1 = fma2(wp1[3], q1.y, s1);           \
            s0 = fma2(wp0[4], q2.x, s0);  s1 = fma2(wp1[4], q2.x, s1);           \
            s0 = fma2(wp0[5], q2.y, s0);  s1 = fma2(wp1[5], q2.y, s1);           \
            s0 = fma2(wp0[6], q3.x, s0);  s1 = fma2(wp1[6], q3.x, s1);           \
            s0 = fma2(wp0[7], q3.y, s0);  s1 = fma2(wp1[7], q3.y, s1);           \
            float2 a0 = unpackf2(s0), a1 = unpackf2(s1);                         \
            float2 o;                                                            \
            o.x = fmaf(1.5f, a0.x + a0.y, HBUF[i].x);                            \
            o.y = fmaf(1.5f, a1.x + a1.y, HBUF[i].y);                            \
            __stcs((float2*)(op + (size_t)((CB) + i) * HW), o);                  \
        }                                                                        \
    }

    LOADB(h0, 0)
    LOADB(h1, UNR)
    LOADB(h2, 2 * UNR)
    for (int cb = 0; cb < C_DIM; cb += 4 * UNR) {
        LOADB(h3, cb + 3 * UNR)
        P2_COMPUTE(h0, cb)
        LOADB_G(h0, cb + 4 * UNR)
        P2_COMPUTE(h1, cb + UNR)
        LOADB_G(h1, cb + 5 * UNR)
        P2_COMPUTE(h2, cb + 2 * UNR)
        LOADB_G(h2, cb + 6 * UNR)
        P2_COMPUTE(h3, cb + 3 * UNR)
    }
}

// ---------------- launch ----------------
extern "C" void kernel_launch(void* const* d_in, const int* in_sizes, int n_in,
                              void* d_out, int out_size) {
    const float* hidden = (const float*)d_in[0];
    const float* emb    = (const float*)d_in[1];
    const float* bbox   = (const float*)d_in[2];
    const float* W1     = (const float*)d_in[3];
    const float* b1v    = (const float*)d_in[4];
    const float* W2     = (const float*)d_in[5];
    const float* b2v    = (const float*)d_in[6];
    float* outp = (float*)d_out;

    mlp1_kernel<<<dim3(C_DIM / 32, M_ROWS / 32), 256>>>(emb, W1, b1v);
    mlp2_kernel<<<dim3(C_DIM / 32, M_ROWS / 32, KCHUNK), 256>>>(W2);
    norm_kernel<<<M_ROWS, 128>>>(b2v);

    cudaFuncSetAttribute(fused_kernel, cudaFuncAttributeMaxDynamicSharedMemorySize,
                         C_DIM * N_ID * (int)sizeof(float));
    fused_kernel<<<288, 128, C_DIM * N_ID * sizeof(float)>>>(hidden, bbox, outp);
}